// round 1
// baseline (speedup 1.0000x reference)
#include <cuda_runtime.h>
#include <math.h>

// Problem constants (fixed by the reference: B=8, T=4096, D=1024)
constexpr int Bb   = 8;
constexpr int Tt   = 4096;
constexpr int Dd   = 1024;
constexpr int Mtot = Bb * Tt;          // 32768 rows
constexpr int NC   = 32;               // scan chunks
constexpr int CL   = Tt / NC;          // 128 steps per chunk

// Scratch (device globals — no allocations allowed in kernel_launch)
__device__ float sc_u[(size_t)Mtot * Dd];   // 128 MB
__device__ float sc_g[(size_t)Mtot * Dd];   // 128 MB
__device__ float sc_h[(size_t)Mtot * Dd];   // 128 MB
__device__ float sc_P[Bb * NC * Dd];
__device__ float sc_S[Bb * NC * Dd];
__device__ float sc_C[Bb * NC * Dd];

// ---------------------------------------------------------------------------
// SGEMM: C[m,n] = sum_k A[m,k] * W[n,k] + bias[n]   (A:[M,K] row-major,
// W:[N,K] row-major -> effectively A @ W^T), optional sigmoid epilogue.
// M=32768, N=K=1024 hardcoded via Dd. Tiles: 128x128x16, 256 thr, 8x8/thread.
// ---------------------------------------------------------------------------
constexpr int BM = 128, BN = 128, BK = 16, TM = 8, TN = 8;

__global__ __launch_bounds__(256, 2)
void sgemm_bias(const float* __restrict__ A, const float* __restrict__ W,
                const float* __restrict__ bias, float* __restrict__ C,
                int act /*0 = none, 1 = sigmoid*/)
{
    __shared__ float As[BK][BM];
    __shared__ float Bs[BK][BN];

    const int tid = threadIdx.x;
    const int bn  = blockIdx.x;          // N tile (0..7)
    const int bm  = blockIdx.y;          // M tile (0..255)

    const float* Ab = A + (size_t)bm * BM * Dd;
    const float* Wb = W + (size_t)bn * BN * Dd;

    // loader mapping: 256 threads -> 64 rows x (4 float4 per row)
    const int lr = tid >> 2;             // 0..63
    const int lc = (tid & 3) << 2;       // 0,4,8,12

    // compute mapping: 16x16 thread grid of 8x8 micro-tiles
    const int tm0 = (tid >> 4) * TM;
    const int tn0 = (tid & 15) * TN;

    float acc[TM][TN] = {};

    for (int k0 = 0; k0 < Dd; k0 += BK) {
        float4 a0 = *reinterpret_cast<const float4*>(Ab + (size_t)lr        * Dd + k0 + lc);
        float4 a1 = *reinterpret_cast<const float4*>(Ab + (size_t)(lr + 64) * Dd + k0 + lc);
        float4 b0 = *reinterpret_cast<const float4*>(Wb + (size_t)lr        * Dd + k0 + lc);
        float4 b1 = *reinterpret_cast<const float4*>(Wb + (size_t)(lr + 64) * Dd + k0 + lc);

        As[lc + 0][lr]      = a0.x; As[lc + 1][lr]      = a0.y;
        As[lc + 2][lr]      = a0.z; As[lc + 3][lr]      = a0.w;
        As[lc + 0][lr + 64] = a1.x; As[lc + 1][lr + 64] = a1.y;
        As[lc + 2][lr + 64] = a1.z; As[lc + 3][lr + 64] = a1.w;

        Bs[lc + 0][lr]      = b0.x; Bs[lc + 1][lr]      = b0.y;
        Bs[lc + 2][lr]      = b0.z; Bs[lc + 3][lr]      = b0.w;
        Bs[lc + 0][lr + 64] = b1.x; Bs[lc + 1][lr + 64] = b1.y;
        Bs[lc + 2][lr + 64] = b1.z; Bs[lc + 3][lr + 64] = b1.w;

        __syncthreads();

        #pragma unroll
        for (int k = 0; k < BK; ++k) {
            float ar[TM], br[TN];
            #pragma unroll
            for (int i = 0; i < TM; ++i) ar[i] = As[k][tm0 + i];
            #pragma unroll
            for (int j = 0; j < TN; ++j) br[j] = Bs[k][tn0 + j];
            #pragma unroll
            for (int i = 0; i < TM; ++i)
                #pragma unroll
                for (int j = 0; j < TN; ++j)
                    acc[i][j] = fmaf(ar[i], br[j], acc[i][j]);
        }
        __syncthreads();
    }

    // epilogue: bias (+ sigmoid), vectorized stores
    float bv[TN];
    #pragma unroll
    for (int j = 0; j < TN; ++j) bv[j] = bias[bn * BN + tn0 + j];

    #pragma unroll
    for (int i = 0; i < TM; ++i) {
        float v[TN];
        #pragma unroll
        for (int j = 0; j < TN; ++j) {
            float t = acc[i][j] + bv[j];
            if (act) t = 1.0f / (1.0f + expf(-t));
            v[j] = t;
        }
        float* row = C + (size_t)(bm * BM + tm0 + i) * Dd + bn * BN + tn0;
        *reinterpret_cast<float4*>(row + 0) = make_float4(v[0], v[1], v[2], v[3]);
        *reinterpret_cast<float4*>(row + 4) = make_float4(v[4], v[5], v[6], v[7]);
    }
}

// ---------------------------------------------------------------------------
// Chunked linear-recurrence scan: h_t = g_t*h_{t-1} + (1-g_t)*u_t
// Phase 1: per (b, chunk, d) compute chunk transfer (P = prod g, S = local h)
// Phase 2: per (b, d) serial combine over 32 chunks -> carry-in per chunk
// Phase 3: replay each chunk from its carry-in, writing h
// ---------------------------------------------------------------------------
__global__ void scan_phase1()
{
    const int d = blockIdx.x * blockDim.x + threadIdx.x;  // 0..1023
    const int c = blockIdx.y;
    const int b = blockIdx.z;
    const size_t base = ((size_t)b * Tt + (size_t)c * CL) * Dd + d;

    float P = 1.0f, S = 0.0f;
    #pragma unroll 4
    for (int t = 0; t < CL; ++t) {
        const float gg = sc_g[base + (size_t)t * Dd];
        const float uu = sc_u[base + (size_t)t * Dd];
        S = fmaf(gg, S, (1.0f - gg) * uu);
        P *= gg;
    }
    const int idx = (b * NC + c) * Dd + d;
    sc_P[idx] = P;
    sc_S[idx] = S;
}

__global__ void scan_phase2()
{
    const int idx = blockIdx.x * blockDim.x + threadIdx.x;  // 0..8191
    const int b = idx >> 10;
    const int d = idx & 1023;

    float carry = 0.0f;
    #pragma unroll
    for (int c = 0; c < NC; ++c) {
        const int k = (b * NC + c) * Dd + d;
        sc_C[k] = carry;
        carry = fmaf(sc_P[k], carry, sc_S[k]);
    }
}

__global__ void scan_phase3()
{
    const int d = blockIdx.x * blockDim.x + threadIdx.x;
    const int c = blockIdx.y;
    const int b = blockIdx.z;
    const size_t base = ((size_t)b * Tt + (size_t)c * CL) * Dd + d;

    float h = sc_C[(b * NC + c) * Dd + d];
    #pragma unroll 4
    for (int t = 0; t < CL; ++t) {
        const float gg = sc_g[base + (size_t)t * Dd];
        const float uu = sc_u[base + (size_t)t * Dd];
        h = fmaf(gg, h, (1.0f - gg) * uu);
        sc_h[base + (size_t)t * Dd] = h;
    }
}

// ---------------------------------------------------------------------------
extern "C" void kernel_launch(void* const* d_in, const int* in_sizes, int n_in,
                              void* d_out, int out_size)
{
    (void)in_sizes; (void)n_in; (void)out_size;

    const float* x  = (const float*)d_in[0];
    const float* Wi = (const float*)d_in[1];
    const float* bi = (const float*)d_in[2];
    const float* Wg = (const float*)d_in[3];
    const float* bg = (const float*)d_in[4];
    const float* Wo = (const float*)d_in[5];
    const float* bo = (const float*)d_in[6];
    float* out = (float*)d_out;

    float *u, *g, *h;
    cudaGetSymbolAddress((void**)&u, sc_u);
    cudaGetSymbolAddress((void**)&g, sc_g);
    cudaGetSymbolAddress((void**)&h, sc_h);

    const dim3 gemm_grid(Dd / BN, Mtot / BM);  // (8, 256)
    const dim3 gemm_blk(256);

    // u = x @ Wi^T + bi ; g = sigmoid(x @ Wg^T + bg)
    sgemm_bias<<<gemm_grid, gemm_blk>>>(x, Wi, bi, u, 0);
    sgemm_bias<<<gemm_grid, gemm_blk>>>(x, Wg, bg, g, 1);

    // chunked scan over T
    const dim3 s_grid(Dd / 256, NC, Bb);  // (4, 32, 8)
    scan_phase1<<<s_grid, 256>>>();
    scan_phase2<<<32, 256>>>();
    scan_phase3<<<s_grid, 256>>>();

    // out = h @ Wo^T + bo
    sgemm_bias<<<gemm_grid, gemm_blk>>>(h, Wo, bo, out, 0);
}

// round 3
// speedup vs baseline: 3.0140x; 3.0140x over previous
#include <cuda_runtime.h>
#include <math.h>
#include <stdint.h>

// Problem constants (fixed by the reference: B=8, T=4096, D=1024)
constexpr int Bb   = 8;
constexpr int Tt   = 4096;
constexpr int Dd   = 1024;
constexpr int Mtot = Bb * Tt;          // 32768 rows
constexpr int NC   = 32;               // scan chunks
constexpr int CL   = Tt / NC;          // 128 steps per chunk

// Scratch (device globals — no allocations allowed in kernel_launch)
__device__ float sc_u[(size_t)Mtot * Dd];
__device__ float sc_g[(size_t)Mtot * Dd];
__device__ float sc_h[(size_t)Mtot * Dd];
__device__ float sc_P[Bb * NC * Dd];
__device__ float sc_S[Bb * NC * Dd];
__device__ float sc_C[Bb * NC * Dd];

// ===========================================================================
// tf32 mma.sync GEMM:  C[m,n] = sum_k A[m,k]*W[n,k] + bias[n]  (+sigmoid)
// Baseline-PTX tensor cores (sm_80 path) — no tcgen05/TMEM (rejected on the
// harness's plain sm_103 PTX target).
// CTA tile 128x128, BK=16. 8 warps, each a 64x32 warp tile = 4x4 m16n8k8.
// cp.async 2-stage double buffer. SMEM rows padded to 20 floats (conflict-
// free for both A-frag and B-frag LDS patterns).
// ===========================================================================
constexpr int BM = 128, BN = 128, BK = 16;
constexpr int NCHUNK = Dd / BK;        // 64
constexpr int LDP    = BK + 4;         // padded row stride (floats)

__device__ __forceinline__ uint32_t smem_u32(const void* p) {
    uint32_t a;
    asm("{ .reg .u64 t; cvta.to.shared.u64 t, %1; cvt.u32.u64 %0, t; }"
        : "=r"(a) : "l"(p));
    return a;
}
__device__ __forceinline__ void cp16(uint32_t s, const void* g) {
    asm volatile("cp.async.cg.shared.global [%0], [%1], 16;" :: "r"(s), "l"(g));
}
__device__ __forceinline__ uint32_t f2tf(float x) {
    uint32_t r;
    asm("cvt.rna.tf32.f32 %0, %1;" : "=r"(r) : "f"(x));
    return r;
}
__device__ __forceinline__ void mma8(float* d, const uint32_t* a, const uint32_t* b) {
    asm volatile(
        "mma.sync.aligned.m16n8k8.row.col.f32.tf32.tf32.f32 "
        "{%0,%1,%2,%3}, {%4,%5,%6,%7}, {%8,%9}, {%0,%1,%2,%3};"
        : "+f"(d[0]), "+f"(d[1]), "+f"(d[2]), "+f"(d[3])
        : "r"(a[0]), "r"(a[1]), "r"(a[2]), "r"(a[3]), "r"(b[0]), "r"(b[1]));
}

__global__ __launch_bounds__(256, 2)
void gemm_tc(const float* __restrict__ A, const float* __restrict__ W,
             const float* __restrict__ bias, float* __restrict__ C, int act)
{
    __shared__ __align__(16) float As[2][BM][LDP];
    __shared__ __align__(16) float Bs[2][BN][LDP];

    const int tid  = threadIdx.x;
    const int wid  = tid >> 5;
    const int lane = tid & 31;
    const int lr   = lane >> 2;          // 0..7
    const int lc   = lane & 3;           // 0..3
    const int bnb  = blockIdx.x;         // N tile (0..7)
    const int bmb  = blockIdx.y;         // M tile (0..255)

    const int wm = (wid >> 2) * 64;      // warp M offset in tile
    const int wn = (wid & 3) * 32;       // warp N offset in tile

    // ---- cp.async loader mapping: 512 float4 per matrix per stage ----
    // thread handles idx = tid and tid+256:  row = idx/4, quad = idx%4
    const int r0 = tid >> 2,  q0 = tid & 3;         // idx0
    const int r1 = r0 + 64;                         // idx1 = tid+256
    const float4* A4 = reinterpret_cast<const float4*>(A) + ((size_t)bmb * BM) * (Dd / 4);
    const float4* B4 = reinterpret_cast<const float4*>(W) + ((size_t)bnb * BN) * (Dd / 4);

    uint32_t sA0[2], sA1[2], sB0[2], sB1[2];
    {
        const uint32_t ab = smem_u32(&As[0][0][0]);
        const uint32_t bb = smem_u32(&Bs[0][0][0]);
        #pragma unroll
        for (int s = 0; s < 2; s++) {
            sA0[s] = ab + ((s * BM + r0) * LDP + q0 * 4) * 4;
            sA1[s] = ab + ((s * BM + r1) * LDP + q0 * 4) * 4;
            sB0[s] = bb + ((s * BN + r0) * LDP + q0 * 4) * 4;
            sB1[s] = bb + ((s * BN + r1) * LDP + q0 * 4) * 4;
        }
    }

    #define LOAD_STAGE(c, s) do {                                            \
        const float4* ga0 = A4 + (size_t)r0 * (Dd / 4) + (c) * 4 + q0;        \
        const float4* ga1 = A4 + (size_t)r1 * (Dd / 4) + (c) * 4 + q0;        \
        const float4* gb0 = B4 + (size_t)r0 * (Dd / 4) + (c) * 4 + q0;        \
        const float4* gb1 = B4 + (size_t)r1 * (Dd / 4) + (c) * 4 + q0;        \
        cp16(sA0[s], ga0); cp16(sA1[s], ga1);                                 \
        cp16(sB0[s], gb0); cp16(sB1[s], gb1);                                 \
        asm volatile("cp.async.commit_group;");                               \
    } while (0)

    float acc[4][4][4] = {};

    LOAD_STAGE(0, 0);
    LOAD_STAGE(1, 1);

    for (int c = 0; c < NCHUNK; c++) {
        const int s = c & 1;
        if (c + 1 < NCHUNK) asm volatile("cp.async.wait_group 1;" ::: "memory");
        else                asm volatile("cp.async.wait_group 0;" ::: "memory");
        __syncthreads();

        #pragma unroll
        for (int ks = 0; ks < 2; ks++) {
            const int k0 = ks * 8;
            uint32_t af[4][4], bf[4][2];
            #pragma unroll
            for (int mi = 0; mi < 4; mi++) {
                const int rr = wm + mi * 16 + lr;
                af[mi][0] = f2tf(As[s][rr    ][k0 + lc]);
                af[mi][1] = f2tf(As[s][rr + 8][k0 + lc]);
                af[mi][2] = f2tf(As[s][rr    ][k0 + lc + 4]);
                af[mi][3] = f2tf(As[s][rr + 8][k0 + lc + 4]);
            }
            #pragma unroll
            for (int ni = 0; ni < 4; ni++) {
                const int nr = wn + ni * 8 + lr;
                bf[ni][0] = f2tf(Bs[s][nr][k0 + lc]);
                bf[ni][1] = f2tf(Bs[s][nr][k0 + lc + 4]);
            }
            #pragma unroll
            for (int mi = 0; mi < 4; mi++)
                #pragma unroll
                for (int ni = 0; ni < 4; ni++)
                    mma8(acc[mi][ni], af[mi], bf[ni]);
        }

        __syncthreads();
        if (c + 2 < NCHUNK) LOAD_STAGE(c + 2, s);
    }

    // ---- epilogue: bias (+sigmoid), float2 stores ----
    #pragma unroll
    for (int ni = 0; ni < 4; ni++) {
        const int gc = bnb * BN + wn + ni * 8 + lc * 2;
        const float b0 = bias[gc], b1 = bias[gc + 1];
        #pragma unroll
        for (int mi = 0; mi < 4; mi++) {
            const size_t gr = (size_t)bmb * BM + wm + mi * 16 + lr;
            float v0 = acc[mi][ni][0] + b0;
            float v1 = acc[mi][ni][1] + b1;
            float v2 = acc[mi][ni][2] + b0;
            float v3 = acc[mi][ni][3] + b1;
            if (act) {
                v0 = 1.0f / (1.0f + expf(-v0));
                v1 = 1.0f / (1.0f + expf(-v1));
                v2 = 1.0f / (1.0f + expf(-v2));
                v3 = 1.0f / (1.0f + expf(-v3));
            }
            *reinterpret_cast<float2*>(C + gr * Dd + gc)       = make_float2(v0, v1);
            *reinterpret_cast<float2*>(C + (gr + 8) * Dd + gc) = make_float2(v2, v3);
        }
    }
    #undef LOAD_STAGE
}

// ---------------------------------------------------------------------------
// Chunked linear-recurrence scan: h_t = g_t*h_{t-1} + (1-g_t)*u_t
// ---------------------------------------------------------------------------
__global__ void scan_phase1()
{
    const int d = blockIdx.x * blockDim.x + threadIdx.x;
    const int c = blockIdx.y;
    const int b = blockIdx.z;
    const size_t base = ((size_t)b * Tt + (size_t)c * CL) * Dd + d;

    float P = 1.0f, S = 0.0f;
    #pragma unroll 4
    for (int t = 0; t < CL; ++t) {
        const float gg = sc_g[base + (size_t)t * Dd];
        const float uu = sc_u[base + (size_t)t * Dd];
        S = fmaf(gg, S, (1.0f - gg) * uu);
        P *= gg;
    }
    const int idx = (b * NC + c) * Dd + d;
    sc_P[idx] = P;
    sc_S[idx] = S;
}

__global__ void scan_phase2()
{
    const int idx = blockIdx.x * blockDim.x + threadIdx.x;
    const int b = idx >> 10;
    const int d = idx & 1023;

    float carry = 0.0f;
    #pragma unroll
    for (int c = 0; c < NC; ++c) {
        const int k = (b * NC + c) * Dd + d;
        sc_C[k] = carry;
        carry = fmaf(sc_P[k], carry, sc_S[k]);
    }
}

__global__ void scan_phase3()
{
    const int d = blockIdx.x * blockDim.x + threadIdx.x;
    const int c = blockIdx.y;
    const int b = blockIdx.z;
    const size_t base = ((size_t)b * Tt + (size_t)c * CL) * Dd + d;

    float h = sc_C[(b * NC + c) * Dd + d];
    #pragma unroll 4
    for (int t = 0; t < CL; ++t) {
        const float gg = sc_g[base + (size_t)t * Dd];
        const float uu = sc_u[base + (size_t)t * Dd];
        h = fmaf(gg, h, (1.0f - gg) * uu);
        sc_h[base + (size_t)t * Dd] = h;
    }
}

// ---------------------------------------------------------------------------
extern "C" void kernel_launch(void* const* d_in, const int* in_sizes, int n_in,
                              void* d_out, int out_size)
{
    (void)in_sizes; (void)n_in; (void)out_size;

    const float* x  = (const float*)d_in[0];
    const float* Wi = (const float*)d_in[1];
    const float* bi = (const float*)d_in[2];
    const float* Wg = (const float*)d_in[3];
    const float* bg = (const float*)d_in[4];
    const float* Wo = (const float*)d_in[5];
    const float* bo = (const float*)d_in[6];
    float* out = (float*)d_out;

    float *u, *g, *h;
    cudaGetSymbolAddress((void**)&u, sc_u);
    cudaGetSymbolAddress((void**)&g, sc_g);
    cudaGetSymbolAddress((void**)&h, sc_h);

    const dim3 ggrid(Dd / BN, Mtot / BM);   // (8, 256)
    const dim3 gblk(256);

    gemm_tc<<<ggrid, gblk>>>(x, Wi, bi, u, 0);
    gemm_tc<<<ggrid, gblk>>>(x, Wg, bg, g, 1);

    const dim3 s_grid(Dd / 256, NC, Bb);    // (4, 32, 8)
    scan_phase1<<<s_grid, 256>>>();
    scan_phase2<<<32, 256>>>();
    scan_phase3<<<s_grid, 256>>>();

    gemm_tc<<<ggrid, gblk>>>(h, Wo, bo, out, 0);
}